// round 6
// baseline (speedup 1.0000x reference)
#include <cuda_runtime.h>
#include <math.h>

// ---------------------------------------------------------------------------
// SpSpMM: C = A @ B, A,B sparse COO (N=4096, NNZ=131072 each), C dense fp32.
//
// R6: scatter products straight to C in L2 via red.global.add.f32
//     (REDG: 1.29 cyc/lane vs smem ATOMS 2.0 cyc/lane -> 0.65x issue cost).
//   0. memset node: zero B-row counters (16 KB)
//   1. init_build: zero C (write-allocate -> C resident in L2, 64MB < 126MB)
//                  fused with B bucket build (vectorized COO loads)
//   2. scatter:    stream A COO; warp gathers B-row bucket contiguously,
//                  fires REDG into C; MLP=2 across A-entry pairs.
// ---------------------------------------------------------------------------

#define NMAX 4096
#define CAP  256           // max nnz per row; Poisson(32) tail => never hit
#define BLK_E 64           // A entries per scatter block

__device__ int  g_cntB[NMAX];
__device__ int2 g_Bbkt[NMAX * CAP];   // .x = col j, .y = bits(val)

__device__ __forceinline__ void red_add_f32(float* p, float v) {
    asm volatile("red.global.add.f32 [%0], %1;" :: "l"(p), "f"(v) : "memory");
}

// ---- 1. fused: zero C (blocks [0,zb)) + build B buckets (blocks [zb,..)) ---
__global__ void __launch_bounds__(256)
init_build_kernel(const int* __restrict__ b_idx,
                  const float* __restrict__ b_val, int nnzB,
                  float* __restrict__ C, int n, int zb) {
    const int tid = threadIdx.x;

    if (blockIdx.x < zb) {
        // zero C with regular stores (write-allocate: lines land in L2)
        const size_t total = ((size_t)n * n) >> 2;
        const size_t step  = (size_t)zb * 256;
        float4 z = make_float4(0.f, 0.f, 0.f, 0.f);
        for (size_t j = (size_t)blockIdx.x * 256 + tid; j < total; j += step)
            ((float4*)C)[j] = z;
        return;
    }

    // build B buckets, 4 entries per thread via int4/float4 loads
    const int quads = nnzB >> 2;
    const int tail  = nnzB & 3;
    int t = (blockIdx.x - zb) * 256 + tid;

    if (t < quads) {
        int4   r = ((const int4*)b_idx)[t];           // rows k
        int4   c = ((const int4*)b_idx)[quads + t];   // cols j (b_idx + nnzB)
        float4 v = ((const float4*)b_val)[t];
        int   rr[4] = {r.x, r.y, r.z, r.w};
        int   cc[4] = {c.x, c.y, c.z, c.w};
        float vv[4] = {v.x, v.y, v.z, v.w};
        #pragma unroll
        for (int j = 0; j < 4; j++) {
            int s = atomicAdd(&g_cntB[rr[j]], 1);
            if (s < CAP)
                g_Bbkt[rr[j] * CAP + s] = make_int2(cc[j], __float_as_int(vv[j]));
        }
    } else if (t < quads + tail) {
        int idx = quads * 4 + (t - quads);
        int rr = b_idx[idx], cc = b_idx[nnzB + idx];
        int s = atomicAdd(&g_cntB[rr], 1);
        if (s < CAP)
            g_Bbkt[rr * CAP + s] = make_int2(cc, __float_as_int(b_val[idx]));
    }
}

// ---- 2. scatter: A COO -> REDG products into C -----------------------------
__global__ void __launch_bounds__(256)
scatter_redg_kernel(const int* __restrict__ a_idx,
                    const float* __restrict__ a_val, int nnzA,
                    float* __restrict__ C, int n) {
    __shared__ int   si[BLK_E];   // row i
    __shared__ int   sk[BLK_E];   // col k
    __shared__ float sv[BLK_E];   // value
    __shared__ int   sm_[BLK_E];  // cntB[k]

    const int tid  = threadIdx.x;
    const int warp = tid >> 5;
    const int lane = tid & 31;
    const int e0   = blockIdx.x * BLK_E;

    // stage BLK_E A-entries (coalesced) + partner counts, one parallel round
    if (tid < BLK_E) {
        int e = e0 + tid;
        if (e < nnzA) {
            int k   = a_idx[nnzA + e];
            si[tid] = a_idx[e];
            sk[tid] = k;
            sv[tid] = a_val[e];
            sm_[tid] = min(g_cntB[k], CAP);
        } else {
            sm_[tid] = 0;
        }
    }
    __syncthreads();

    // warp handles entries e and e+8 together (MLP=2: both B-bucket loads in
    // flight before the REDGs). e in {w, w+16, w+32, w+48}; e+8 covers rest.
    for (int e = warp; e < BLK_E; e += 16) {
        const int e2 = e + 8;
        const int   m1 = sm_[e];
        const int   m2 = sm_[e2];
        const int   k1 = sk[e];
        const int   k2 = sk[e2];
        const float a1 = sv[e];
        const float a2 = sv[e2];
        float* row1 = C + (size_t)si[e]  * n;
        float* row2 = C + (size_t)si[e2] * n;
        const int mm = m1 > m2 ? m1 : m2;

        for (int t = lane; t < mm; t += 32) {
            int2 q1, q2;
            const bool l1 = (t < m1);
            const bool l2 = (t < m2);
            if (l1) q1 = g_Bbkt[k1 * CAP + t];      // coalesced 8B/lane
            if (l2) q2 = g_Bbkt[k2 * CAP + t];
            if (l1) red_add_f32(row1 + q1.x, a1 * __int_as_float(q1.y));
            if (l2) red_add_f32(row2 + q2.x, a2 * __int_as_float(q2.y));
        }
    }
}

// ---------------------------------------------------------------------------
extern "C" void kernel_launch(void* const* d_in, const int* in_sizes, int n_in,
                              void* d_out, int out_size) {
    const int*   a_idx = (const int*)  d_in[0];
    const float* a_val = (const float*)d_in[1];
    const int*   b_idx = (const int*)  d_in[2];
    const float* b_val = (const float*)d_in[3];
    float*       C     = (float*)d_out;

    const int nnzA = in_sizes[1];
    const int nnzB = in_sizes[3];
    const int n    = (int)(sqrt((double)out_size) + 0.5);

    // 0. zero B-row counters (single tiny memset node)
    void* cnt_ptr = nullptr;
    cudaGetSymbolAddress(&cnt_ptr, g_cntB);
    cudaMemsetAsync(cnt_ptr, 0, NMAX * sizeof(int));

    // 1. fused zero-C + build-B
    {
        const int zb          = 2048;                     // C-zeroing blocks
        const int build_items = (nnzB >> 2) + (nnzB & 3);
        const int bb          = (build_items + 255) / 256;
        init_build_kernel<<<zb + bb, 256>>>(b_idx, b_val, nnzB, C, n, zb);
    }

    // 2. scatter products via REDG
    {
        const int blocks = (nnzA + BLK_E - 1) / BLK_E;
        scatter_redg_kernel<<<blocks, 256>>>(a_idx, a_val, nnzA, C, n);
    }
}